// round 3
// baseline (speedup 1.0000x reference)
#include <cuda_runtime.h>
#include <cuda_bf16.h>
#include <math.h>

// Problem constants
#define Bq   4
#define Tq   8192
#define Dq   1024
#define DS   64
#define CHq  128
#define Cq   64
#define ROWS (Bq * Tq)
#define OUT_ELEMS ((size_t)ROWS * Dq)

// ---------------- scratch ----------------
__device__ float g_xs[ROWS * Dq];
__device__ float g_wkv[ROWS * DS];
__device__ float g_hs[ROWS * DS];
__device__ float g_mu[ROWS];
__device__ float g_rstd[ROWS];
__device__ float g_W2[Dq * 128];      // interleaved: [k][2j]=g*Wk[:,j], [k][2j+1]=g*Wv[:,j]
__device__ float g_csum[128];
__device__ float g_bsum[128];
__device__ float g_gate[Dq];
__device__ float g_wvec[DS];
__device__ float g_efvec[DS];
__device__ float g_c1[CHq * DS];
__device__ float g_c2[Cq * DS];
__device__ float g_cs[Bq * Cq * DS];

// ---------------------------------------------------------------------------
__global__ void prep_kernel(const float* __restrict__ td, const float* __restrict__ tf,
                            const float* __restrict__ Wk, const float* __restrict__ Wv,
                            const float* __restrict__ ln_g, const float* __restrict__ ln_b,
                            const float* __restrict__ sg) {
    int n = threadIdx.x;  // 128 threads
    if (n < DS) {
        g_wvec[n]  = expf(td[n]);
        g_efvec[n] = expf(tf[n]);
    }
    for (int i = n; i < Dq; i += 128)
        g_gate[i] = 1.f / (1.f + expf(-sg[i]));

    int j = n >> 1, isv = n & 1;   // interleaved channel mapping
    float cs = 0.f, bs = 0.f;
    for (int k = 0; k < Dq; k++) {
        float wv = isv ? Wv[k * DS + j] : Wk[k * DS + j];
        float gk = ln_g[k];
        g_W2[k * 128 + n] = gk * wv;
        cs += gk * wv;
        bs += ln_b[k] * wv;
    }
    g_csum[n] = cs;
    g_bsum[n] = bs;
}

// ---------------------------------------------------------------------------
__global__ void coef_kernel(const float* __restrict__ td) {
    int ch = blockIdx.x;     // 64
    int d  = threadIdx.x;    // 128
    __shared__ float p[CHq];
    float w = expf(td[ch]);
    p[d] = (d == 0) ? 1.f : 0.f;
    __syncthreads();
    for (int s = 1; s < CHq; s++) {
        float tmp = (d >= s) ? p[d - s] : 0.f;
        __syncthreads();
        if (d >= s) p[d] += w * tmp;
        __syncthreads();
    }
    g_c1[d * DS + ch] = p[d];

    float wc = expf(128.f * td[ch]);
    __syncthreads();
    if (d < Cq) p[d] = (d == 0) ? 1.f : 0.f;
    __syncthreads();
    for (int s = 1; s < Cq; s++) {
        float tmp = (d >= s && d < Cq) ? p[d - s] : 0.f;
        __syncthreads();
        if (d >= s && d < Cq) p[d] += wc * tmp;
        __syncthreads();
    }
    if (d < Cq) g_c2[d * DS + ch] = p[d];
}

// ---------------------------------------------------------------------------
// Tensor-core bf16x3 GEMM machinery
// ---------------------------------------------------------------------------
__device__ __forceinline__ unsigned sptr(const void* p) {
    return (unsigned)__cvta_generic_to_shared(p);
}
__device__ __forceinline__ void ldsm4(unsigned* r, unsigned a) {
    asm volatile("ldmatrix.sync.aligned.m8n8.x4.shared.b16 {%0,%1,%2,%3},[%4];"
                 : "=r"(r[0]), "=r"(r[1]), "=r"(r[2]), "=r"(r[3]) : "r"(a));
}
__device__ __forceinline__ void ldsm4t(unsigned* r, unsigned a) {
    asm volatile("ldmatrix.sync.aligned.m8n8.x4.trans.shared.b16 {%0,%1,%2,%3},[%4];"
                 : "=r"(r[0]), "=r"(r[1]), "=r"(r[2]), "=r"(r[3]) : "r"(a));
}
__device__ __forceinline__ void mma_bf(float* c, const unsigned* a, unsigned b0, unsigned b1) {
    asm volatile("mma.sync.aligned.m16n8k16.row.col.f32.bf16.bf16.f32 "
                 "{%0,%1,%2,%3},{%4,%5,%6,%7},{%8,%9},{%0,%1,%2,%3};"
                 : "+f"(c[0]), "+f"(c[1]), "+f"(c[2]), "+f"(c[3])
                 : "r"(a[0]), "r"(a[1]), "r"(a[2]), "r"(a[3]), "r"(b0), "r"(b1));
}
__device__ __forceinline__ void split2(float v0, float v1, __nv_bfloat162& h, __nv_bfloat162& l) {
    __nv_bfloat16 h0 = __float2bfloat16(v0);
    __nv_bfloat16 h1 = __float2bfloat16(v1);
    __nv_bfloat16 l0 = __float2bfloat16(v0 - __bfloat162float(h0));
    __nv_bfloat16 l1 = __float2bfloat16(v1 - __bfloat162float(h1));
    h = __halves2bfloat162(h0, h1);
    l = __halves2bfloat162(l0, l1);
}

#define AP 24    // A smem row pitch in bf16 (48B: conflict-free for LDSM columns)
#define BP 136   // B smem row pitch in bf16 (272B: conflict-free for LDSM.trans)

// MODE 0: x_shift GEMM (A = x_cat, B = Wshift, epilogue = gate mix, out g_xs)
// MODE 1: kv GEMM      (A = g_xs,  B = g_W2,   epilogue = LN-fold + wkv, out g_wkv)
template <int MODE>
__global__ __launch_bounds__(256, 1)
void gemm_tc(const float* __restrict__ x, const float* __restrict__ Wsh) {
    __shared__ __nv_bfloat16 As[2][2][128 * AP];  // [stage][hi/lo]
    __shared__ __nv_bfloat16 Bs[2][2][16 * BP];

    const int t = threadIdx.x;
    const int lane = t & 31;
    const int wid = t >> 5;
    const int wm = (wid >> 2) * 64;
    const int wn = (wid & 3) * 32;
    const int bm = (MODE == 0 ? blockIdx.y : blockIdx.x) * 128;
    const int bn = (MODE == 0 ? blockIdx.x * 128 : 0);

    // global A row pointers (two rows per thread: r0, r0+64)
    const float* aptr0;
    const float* aptr1;
    {
        int r0 = bm + (t >> 2), r1 = r0 + 64;
        if (MODE == 0) {
            int s0 = ((r0 >> 13) << 13) | (((r0 & (Tq - 1)) + Tq / 2) & (Tq - 1));
            int s1 = ((r1 >> 13) << 13) | (((r1 & (Tq - 1)) + Tq / 2) & (Tq - 1));
            aptr0 = x + (size_t)s0 * Dq + (t & 3) * 4;
            aptr1 = x + (size_t)s1 * Dq + (t & 3) * 4;
        } else {
            aptr0 = g_xs + (size_t)r0 * Dq + (t & 3) * 4;
            aptr1 = g_xs + (size_t)r1 * Dq + (t & 3) * 4;
        }
    }
    const float* bptr = (MODE == 0)
        ? Wsh + (size_t)(t >> 4) * Dq + bn + (t & 15) * 8
        : g_W2 + (size_t)(t >> 4) * 128 + (t & 15) * 8;
    const size_t bstep = (MODE == 0 ? (size_t)16 * Dq : (size_t)16 * 128);

    const int aIdx = (t >> 2) * AP + (t & 3) * 4;
    const int bIdx = (t >> 4) * BP + (t & 15) * 8;

    const unsigned aoff = (unsigned)(((lane & 15) * AP + ((lane >> 4) << 3)) * 2);
    const unsigned boff = (unsigned)(((lane & 15) * BP + wn + ((lane >> 4) << 3)) * 2);

    float acc[4][4][4];
#pragma unroll
    for (int i = 0; i < 4; i++)
#pragma unroll
        for (int j = 0; j < 4; j++)
#pragma unroll
            for (int e = 0; e < 4; e++) acc[i][j][e] = 0.f;

    float4 rA0, rA1, rB0, rB1;

    auto LD = [&](int kc) {
        rA0 = *(const float4*)(aptr0 + (size_t)kc * 16);
        rA1 = *(const float4*)(aptr1 + (size_t)kc * 16);
        rB0 = *(const float4*)(bptr + (size_t)kc * bstep);
        rB1 = *(const float4*)(bptr + (size_t)kc * bstep + 4);
    };
    auto STS = [&](int s) {
        __nv_bfloat162 h, l;
        split2(rA0.x, rA0.y, h, l);
        *(__nv_bfloat162*)&As[s][0][aIdx] = h;
        *(__nv_bfloat162*)&As[s][1][aIdx] = l;
        split2(rA0.z, rA0.w, h, l);
        *(__nv_bfloat162*)&As[s][0][aIdx + 2] = h;
        *(__nv_bfloat162*)&As[s][1][aIdx + 2] = l;
        split2(rA1.x, rA1.y, h, l);
        *(__nv_bfloat162*)&As[s][0][aIdx + 64 * AP] = h;
        *(__nv_bfloat162*)&As[s][1][aIdx + 64 * AP] = l;
        split2(rA1.z, rA1.w, h, l);
        *(__nv_bfloat162*)&As[s][0][aIdx + 64 * AP + 2] = h;
        *(__nv_bfloat162*)&As[s][1][aIdx + 64 * AP + 2] = l;

        split2(rB0.x, rB0.y, h, l);
        *(__nv_bfloat162*)&Bs[s][0][bIdx] = h;
        *(__nv_bfloat162*)&Bs[s][1][bIdx] = l;
        split2(rB0.z, rB0.w, h, l);
        *(__nv_bfloat162*)&Bs[s][0][bIdx + 2] = h;
        *(__nv_bfloat162*)&Bs[s][1][bIdx + 2] = l;
        split2(rB1.x, rB1.y, h, l);
        *(__nv_bfloat162*)&Bs[s][0][bIdx + 4] = h;
        *(__nv_bfloat162*)&Bs[s][1][bIdx + 4] = l;
        split2(rB1.z, rB1.w, h, l);
        *(__nv_bfloat162*)&Bs[s][0][bIdx + 6] = h;
        *(__nv_bfloat162*)&Bs[s][1][bIdx + 6] = l;
    };

    LD(0);
    STS(0);

    const int NCHUNK = Dq / 16;  // 64
    for (int kc = 0; kc < NCHUNK; kc++) {
        __syncthreads();
        if (kc + 1 < NCHUNK) LD(kc + 1);

        const int s = kc & 1;
        const unsigned aHi = sptr(&As[s][0][0]);
        const unsigned aLo = sptr(&As[s][1][0]);
        const unsigned bHi = sptr(&Bs[s][0][0]);
        const unsigned bLo = sptr(&Bs[s][1][0]);

        unsigned ah[4][4], al[4][4], bh[2][4], bl[2][4];
#pragma unroll
        for (int mt = 0; mt < 4; mt++) {
            unsigned off = (unsigned)((wm + mt * 16) * AP * 2) + aoff;
            ldsm4(ah[mt], aHi + off);
            ldsm4(al[mt], aLo + off);
        }
#pragma unroll
        for (int ng = 0; ng < 2; ng++) {
            unsigned off = boff + ng * 32;
            ldsm4t(bh[ng], bHi + off);
            ldsm4t(bl[ng], bLo + off);
        }
#pragma unroll
        for (int mt = 0; mt < 4; mt++)
#pragma unroll
            for (int nt = 0; nt < 4; nt++) {
                const int ng = nt >> 1, p = (nt & 1) * 2;
                mma_bf(acc[mt][nt], ah[mt], bh[ng][p], bh[ng][p + 1]);
                mma_bf(acc[mt][nt], ah[mt], bl[ng][p], bl[ng][p + 1]);
                mma_bf(acc[mt][nt], al[mt], bh[ng][p], bh[ng][p + 1]);
            }

        if (kc + 1 < NCHUNK) STS((kc + 1) & 1);
    }

    // ---------------- epilogue ----------------
#pragma unroll
    for (int mt = 0; mt < 4; mt++) {
        const int r0 = bm + wm + mt * 16 + (lane >> 2);
        if (MODE == 0) {
#pragma unroll
            for (int nt = 0; nt < 4; nt++) {
                const int col = bn + wn + nt * 8 + (lane & 3) * 2;
                float2 g2 = *(const float2*)&g_gate[col];
                float2 xv = *(const float2*)&x[(size_t)r0 * Dq + col];
                float2 o;
                o.x = fmaf(acc[mt][nt][0] - xv.x, g2.x, xv.x);
                o.y = fmaf(acc[mt][nt][1] - xv.y, g2.y, xv.y);
                *(float2*)&g_xs[(size_t)r0 * Dq + col] = o;
                float2 xw = *(const float2*)&x[(size_t)(r0 + 8) * Dq + col];
                o.x = fmaf(acc[mt][nt][2] - xw.x, g2.x, xw.x);
                o.y = fmaf(acc[mt][nt][3] - xw.y, g2.y, xw.y);
                *(float2*)&g_xs[(size_t)(r0 + 8) * Dq + col] = o;
            }
        } else {
            const float mu0 = g_mu[r0], rs0 = g_rstd[r0];
            const float mu1 = g_mu[r0 + 8], rs1 = g_rstd[r0 + 8];
#pragma unroll
            for (int nt = 0; nt < 4; nt++) {
                const int col = wn + nt * 8 + (lane & 3) * 2;  // even
                const int ch = col >> 1;
                const float cs0 = g_csum[col], cs1 = g_csum[col + 1];
                const float bs0 = g_bsum[col], bs1 = g_bsum[col + 1];
                const float ef = g_efvec[ch];
                {
                    float kk = rs0 * (acc[mt][nt][0] - mu0 * cs0) + bs0;
                    float vv = rs0 * (acc[mt][nt][1] - mu0 * cs1) + bs1;
                    float sig = 1.f / (1.f + expf(-kk));
                    g_wkv[(size_t)r0 * DS + ch] = expf(-ef * sig) * vv;
                }
                {
                    float kk = rs1 * (acc[mt][nt][2] - mu1 * cs0) + bs0;
                    float vv = rs1 * (acc[mt][nt][3] - mu1 * cs1) + bs1;
                    float sig = 1.f / (1.f + expf(-kk));
                    g_wkv[(size_t)(r0 + 8) * DS + ch] = expf(-ef * sig) * vv;
                }
            }
        }
    }
}

// ---------------------------------------------------------------------------
__global__ void stats_kernel() {
    int row = blockIdx.x;
    const float4* xr = (const float4*)(g_xs + (size_t)row * Dq);
    float4 v = xr[threadIdx.x];
    float s  = v.x + v.y + v.z + v.w;
    float s2 = v.x * v.x + v.y * v.y + v.z * v.z + v.w * v.w;
#pragma unroll
    for (int o = 16; o; o >>= 1) {
        s  += __shfl_xor_sync(0xffffffffu, s, o);
        s2 += __shfl_xor_sync(0xffffffffu, s2, o);
    }
    __shared__ float ss[8], ss2[8];
    int w = threadIdx.x >> 5, l = threadIdx.x & 31;
    if (l == 0) { ss[w] = s; ss2[w] = s2; }
    __syncthreads();
    if (threadIdx.x == 0) {
        float S = 0.f, S2 = 0.f;
#pragma unroll
        for (int i = 0; i < 8; i++) { S += ss[i]; S2 += ss2[i]; }
        float mu  = S * (1.f / 1024.f);
        float var = S2 * (1.f / 1024.f) - mu * mu;
        g_mu[row]   = mu;
        g_rstd[row] = rsqrtf(var + 1e-5f);
    }
}

// ---------------------------------------------------------------------------
__global__ void scan_kernel() {
    int bc = blockIdx.x;
    int ch = threadIdx.x;
    float w = g_wvec[ch];
    size_t base = (size_t)bc * CHq * DS + ch;
    float h = 0.f;
    for (int i = 0; i < CHq; i++) {
        h = fmaf(h, w, g_wkv[base + (size_t)i * DS]);
        g_hs[base + (size_t)i * DS] = h;
    }
}

// ---------------------------------------------------------------------------
__global__ __launch_bounds__(256, 2)
void out_gemm(const float* __restrict__ Wo, float* __restrict__ out) {
    __shared__ float As2[8][128];
    __shared__ float Bs2[8][128];
    const int tid = threadIdx.x;
    const int tx = tid & 15, ty = tid >> 4;
    const int bm = blockIdx.y * 128, bn = blockIdx.x * 128;
    const int aRow = tid >> 1, aCol = (tid & 1) * 4;
    const int bRow = tid >> 5, bCol = (tid & 31) * 4;
    const float* Aptr = g_hs + (size_t)(bm + aRow) * DS;
    const float* Bptr = Wo + (size_t)bRow * Dq + bn + bCol;

    float acc[8][8];
#pragma unroll
    for (int i = 0; i < 8; i++)
#pragma unroll
        for (int j = 0; j < 8; j++) acc[i][j] = 0.f;

#pragma unroll
    for (int k0 = 0; k0 < DS; k0 += 8) {
        float4 av = *(const float4*)(Aptr + k0 + aCol);
        As2[aCol + 0][aRow] = av.x;
        As2[aCol + 1][aRow] = av.y;
        As2[aCol + 2][aRow] = av.z;
        As2[aCol + 3][aRow] = av.w;
        *(float4*)&Bs2[bRow][bCol] = *(const float4*)(Bptr + (size_t)k0 * Dq);
        __syncthreads();
#pragma unroll
        for (int kk = 0; kk < 8; kk++) {
            float4 a0 = *(float4*)&As2[kk][ty * 8];
            float4 a1 = *(float4*)&As2[kk][ty * 8 + 4];
            float4 b0 = *(float4*)&Bs2[kk][tx * 8];
            float4 b1 = *(float4*)&Bs2[kk][tx * 8 + 4];
            float a[8] = {a0.x, a0.y, a0.z, a0.w, a1.x, a1.y, a1.z, a1.w};
            float b[8] = {b0.x, b0.y, b0.z, b0.w, b1.x, b1.y, b1.z, b1.w};
#pragma unroll
            for (int i = 0; i < 8; i++)
#pragma unroll
                for (int j = 0; j < 8; j++) acc[i][j] = fmaf(a[i], b[j], acc[i][j]);
        }
        __syncthreads();
    }

#pragma unroll
    for (int i = 0; i < 8; i++) {
        int row = bm + ty * 8 + i;
        float4 o0 = {acc[i][0], acc[i][1], acc[i][2], acc[i][3]};
        float4 o1 = {acc[i][4], acc[i][5], acc[i][6], acc[i][7]};
        float4* op = (float4*)(out + (size_t)row * Dq + bn + tx * 8);
        op[0] = o0;
        op[1] = o1;
    }
}

// ---------------------------------------------------------------------------
__global__ void cstate_kernel() {
    int bc = blockIdx.x;
    int ch = threadIdx.x;
    const float* base = g_wkv + (size_t)bc * CHq * DS + ch;
    float s = 0.f;
    for (int d = 0; d < CHq; d++)
        s = fmaf(g_c1[d * DS + ch], base[(size_t)(CHq - 1 - d) * DS], s);
    g_cs[bc * DS + ch] = s;
}

__global__ void lstate_kernel(float* __restrict__ outls) {
    int b = blockIdx.x;
    int ch = threadIdx.x;
    float s = 0.f;
    for (int e = 0; e < Cq; e++)
        s = fmaf(g_c2[e * DS + ch], g_cs[((size_t)b * Cq + (Cq - 1 - e)) * DS + ch], s);
    outls[b * DS + ch] = s;
}

// ---------------------------------------------------------------------------
extern "C" void kernel_launch(void* const* d_in, const int* in_sizes, int n_in,
                              void* d_out, int out_size) {
    const float* x   = (const float*)d_in[0];
    const float* td  = (const float*)d_in[1];
    const float* tf  = (const float*)d_in[2];
    const float* Wk  = (const float*)d_in[3];
    const float* Wv  = (const float*)d_in[4];
    const float* Wo  = (const float*)d_in[5];
    const float* Wsh = (const float*)d_in[6];
    const float* sg  = (const float*)d_in[7];
    const float* lng = (const float*)d_in[8];
    const float* lnb = (const float*)d_in[9];
    float* out = (float*)d_out;

    prep_kernel<<<1, 128>>>(td, tf, Wk, Wv, lng, lnb, sg);
    coef_kernel<<<64, 128>>>(td);
    gemm_tc<0><<<dim3(Dq / 128, ROWS / 128), 256>>>(x, Wsh);
    stats_kernel<<<ROWS, 256>>>();
    gemm_tc<1><<<ROWS / 128, 256>>>(x, Wsh);
    scan_kernel<<<Bq * Cq, DS>>>();
    out_gemm<<<dim3(Dq / 128, ROWS / 128), 256>>>(Wo, out);
    cstate_kernel<<<Bq * Cq, DS>>>();
    if ((size_t)out_size >= OUT_ELEMS + (size_t)Bq * DS) {
        lstate_kernel<<<Bq, DS>>>(out + OUT_ELEMS);
    }
}

// round 4
// speedup vs baseline: 1.2327x; 1.2327x over previous
#include <cuda_runtime.h>
#include <cuda_bf16.h>
#include <math.h>

// Problem constants
#define Bq   4
#define Tq   8192
#define Dq   1024
#define DS   64
#define CHq  128
#define Cq   64
#define ROWS (Bq * Tq)
#define OUT_ELEMS ((size_t)ROWS * Dq)

// ---------------- scratch ----------------
__device__ __nv_bfloat16 g_xh[ROWS * Dq];    // x split hi
__device__ __nv_bfloat16 g_xl[ROWS * Dq];    // x split lo
__device__ __nv_bfloat16 g_xsh[ROWS * Dq];   // x_shift hi
__device__ __nv_bfloat16 g_xsl[ROWS * Dq];   // x_shift lo
__device__ __nv_bfloat16 g_wshh[Dq * Dq];    // Wshift hi
__device__ __nv_bfloat16 g_wshl[Dq * Dq];    // Wshift lo
__device__ __nv_bfloat16 g_woh[DS * Dq];     // Wo hi
__device__ __nv_bfloat16 g_wol[DS * Dq];     // Wo lo
__device__ __nv_bfloat16 g_W2h[Dq * 128];    // interleaved g*[Wk|Wv] hi
__device__ __nv_bfloat16 g_W2l[Dq * 128];    // interleaved g*[Wk|Wv] lo
__device__ __nv_bfloat16 g_hsh[ROWS * DS];   // hs hi
__device__ __nv_bfloat16 g_hsl[ROWS * DS];   // hs lo
__device__ float g_wkv[ROWS * DS];
__device__ float g_mu[ROWS];
__device__ float g_rstd[ROWS];
__device__ float g_csum[128];
__device__ float g_bsum[128];
__device__ float g_gate[Dq];
__device__ float g_wvec[DS];
__device__ float g_efvec[DS];
__device__ float g_c1[CHq * DS];
__device__ float g_c2[Cq * DS];
__device__ float g_cs[Bq * Cq * DS];

// ---------------------------------------------------------------------------
__device__ __forceinline__ void split2(float v0, float v1, __nv_bfloat162& h, __nv_bfloat162& l) {
    __nv_bfloat16 h0 = __float2bfloat16(v0);
    __nv_bfloat16 h1 = __float2bfloat16(v1);
    __nv_bfloat16 l0 = __float2bfloat16(v0 - __bfloat162float(h0));
    __nv_bfloat16 l1 = __float2bfloat16(v1 - __bfloat162float(h1));
    h = __halves2bfloat162(h0, h1);
    l = __halves2bfloat162(l0, l1);
}

// generic fp32 -> (hi, lo) bf16 split
__global__ void conv_split(const float* __restrict__ in, __nv_bfloat16* __restrict__ hi,
                           __nv_bfloat16* __restrict__ lo) {
    int i = blockIdx.x * blockDim.x + threadIdx.x;
    float4 v = ((const float4*)in)[i];
    __nv_bfloat162 h0, l0, h1, l1;
    split2(v.x, v.y, h0, l0);
    split2(v.z, v.w, h1, l1);
    ((__nv_bfloat162*)hi)[2 * i]     = h0;
    ((__nv_bfloat162*)hi)[2 * i + 1] = h1;
    ((__nv_bfloat162*)lo)[2 * i]     = l0;
    ((__nv_bfloat162*)lo)[2 * i + 1] = l1;
}

// ---------------------------------------------------------------------------
__global__ void prep_kernel(const float* __restrict__ td, const float* __restrict__ tf,
                            const float* __restrict__ Wk, const float* __restrict__ Wv,
                            const float* __restrict__ ln_g, const float* __restrict__ ln_b,
                            const float* __restrict__ sg) {
    int n = threadIdx.x;  // 128 threads
    if (n < DS) {
        g_wvec[n]  = expf(td[n]);
        g_efvec[n] = expf(tf[n]);
    }
    for (int i = n; i < Dq; i += 128)
        g_gate[i] = 1.f / (1.f + expf(-sg[i]));

    int j = n >> 1, isv = n & 1;
    float cs = 0.f, bs = 0.f;
    for (int k = 0; k < Dq; k++) {
        float wv = isv ? Wv[k * DS + j] : Wk[k * DS + j];
        float gk = ln_g[k];
        float w2 = gk * wv;
        __nv_bfloat16 h = __float2bfloat16(w2);
        g_W2h[k * 128 + n] = h;
        g_W2l[k * 128 + n] = __float2bfloat16(w2 - __bfloat162float(h));
        cs += w2;
        bs += ln_b[k] * wv;
    }
    g_csum[n] = cs;
    g_bsum[n] = bs;
}

// ---------------------------------------------------------------------------
__global__ void coef_kernel(const float* __restrict__ td) {
    int ch = blockIdx.x;
    int d  = threadIdx.x;
    __shared__ float p[CHq];
    float w = expf(td[ch]);
    p[d] = (d == 0) ? 1.f : 0.f;
    __syncthreads();
    for (int s = 1; s < CHq; s++) {
        float tmp = (d >= s) ? p[d - s] : 0.f;
        __syncthreads();
        if (d >= s) p[d] += w * tmp;
        __syncthreads();
    }
    g_c1[d * DS + ch] = p[d];

    float wc = expf(128.f * td[ch]);
    __syncthreads();
    if (d < Cq) p[d] = (d == 0) ? 1.f : 0.f;
    __syncthreads();
    for (int s = 1; s < Cq; s++) {
        float tmp = (d >= s && d < Cq) ? p[d - s] : 0.f;
        __syncthreads();
        if (d >= s && d < Cq) p[d] += wc * tmp;
        __syncthreads();
    }
    if (d < Cq) g_c2[d * DS + ch] = p[d];
}

// ---------------------------------------------------------------------------
// tensor-core machinery
// ---------------------------------------------------------------------------
__device__ __forceinline__ unsigned sptr(const void* p) {
    return (unsigned)__cvta_generic_to_shared(p);
}
__device__ __forceinline__ void ldsm4(unsigned* r, unsigned a) {
    asm volatile("ldmatrix.sync.aligned.m8n8.x4.shared.b16 {%0,%1,%2,%3},[%4];"
                 : "=r"(r[0]), "=r"(r[1]), "=r"(r[2]), "=r"(r[3]) : "r"(a));
}
__device__ __forceinline__ void ldsm4t(unsigned* r, unsigned a) {
    asm volatile("ldmatrix.sync.aligned.m8n8.x4.trans.shared.b16 {%0,%1,%2,%3},[%4];"
                 : "=r"(r[0]), "=r"(r[1]), "=r"(r[2]), "=r"(r[3]) : "r"(a));
}
__device__ __forceinline__ void mma_bf(float* c, const unsigned* a, unsigned b0, unsigned b1) {
    asm volatile("mma.sync.aligned.m16n8k16.row.col.f32.bf16.bf16.f32 "
                 "{%0,%1,%2,%3},{%4,%5,%6,%7},{%8,%9},{%0,%1,%2,%3};"
                 : "+f"(c[0]), "+f"(c[1]), "+f"(c[2]), "+f"(c[3])
                 : "r"(a[0]), "r"(a[1]), "r"(a[2]), "r"(a[3]), "r"(b0), "r"(b1));
}
__device__ __forceinline__ void cp16(unsigned s, const void* g) {
    asm volatile("cp.async.cg.shared.global [%0],[%1],16;\n" :: "r"(s), "l"(g));
}

#define AP 24    // A smem pitch (bf16)
#define BP 136   // B smem pitch (bf16)
#define ABYTES (128 * AP * 2)     // 6144
#define BBYTES (16 * BP * 2)      // 4352

// MODE 0: x_shift GEMM; MODE 1: kv GEMM; MODE 2: out GEMM
template <int MODE>
__global__ __launch_bounds__(256, 2)
void gemm_tc(const float* __restrict__ x, float* __restrict__ out) {
    __shared__ __nv_bfloat16 As[2][2][128 * AP];
    __shared__ __nv_bfloat16 Bs[2][2][16 * BP];

    const int t = threadIdx.x;
    const int lane = t & 31;
    const int wid = t >> 5;
    const int wm = (wid >> 2) * 64;
    const int wn = (wid & 3) * 32;
    const int bm = (MODE == 1 ? blockIdx.x : blockIdx.y) * 128;
    const int bn = (MODE == 1 ? 0 : blockIdx.x * 128);
    const int NCH = (MODE == 2 ? 4 : 64);

    // global pointers (pre-split bf16)
    const __nv_bfloat16 *Ah, *Al, *Bh, *Bl;
    size_t bpitch;
    {
        int r = bm + (t >> 1);
        if (MODE == 0) {
            int s = ((r >> 13) << 13) | (((r & (Tq - 1)) + Tq / 2) & (Tq - 1));
            Ah = g_xh + (size_t)s * Dq;
            Al = g_xl + (size_t)s * Dq;
        } else if (MODE == 1) {
            Ah = g_xsh + (size_t)r * Dq;
            Al = g_xsl + (size_t)r * Dq;
        } else {
            Ah = g_hsh + (size_t)r * DS;
            Al = g_hsl + (size_t)r * DS;
        }
        Ah += (t & 1) * 8;
        Al += (t & 1) * 8;
    }
    if (MODE == 0)      { Bh = g_wshh; Bl = g_wshl; bpitch = Dq;  }
    else if (MODE == 1) { Bh = g_W2h;  Bl = g_W2l;  bpitch = 128; }
    else                { Bh = g_woh;  Bl = g_wol;  bpitch = Dq;  }
    Bh += (size_t)(t >> 4) * bpitch + bn + (t & 15) * 8;
    Bl += (size_t)(t >> 4) * bpitch + bn + (t & 15) * 8;

    const unsigned aST = sptr(&As[0][0][0]) + (unsigned)(((t >> 1) * AP + (t & 1) * 8) * 2);
    const unsigned bST = sptr(&Bs[0][0][0]) + (unsigned)(((t >> 4) * BP + (t & 15) * 8) * 2);

    const unsigned aoff = (unsigned)(((lane & 15) * AP + ((lane >> 4) << 3)) * 2);
    const unsigned boff = (unsigned)(((lane & 15) * BP + wn + ((lane >> 4) << 3)) * 2);

    float acc[4][4][4];
#pragma unroll
    for (int i = 0; i < 4; i++)
#pragma unroll
        for (int j = 0; j < 4; j++)
#pragma unroll
            for (int e = 0; e < 4; e++) acc[i][j][e] = 0.f;

    auto LOAD = [&](int kc) {
        const int s = kc & 1;
        unsigned a0 = aST + (unsigned)(s * 2 * ABYTES);
        cp16(a0,          Ah + (size_t)kc * 16);
        cp16(a0 + ABYTES, Al + (size_t)kc * 16);
        unsigned b0 = bST + (unsigned)(s * 2 * BBYTES);
        cp16(b0,          Bh + (size_t)kc * 16 * bpitch);
        cp16(b0 + BBYTES, Bl + (size_t)kc * 16 * bpitch);
        asm volatile("cp.async.commit_group;\n" ::);
    };

    LOAD(0);
    for (int kc = 0; kc < NCH; kc++) {
        if (kc + 1 < NCH) {
            LOAD(kc + 1);
            asm volatile("cp.async.wait_group 1;\n" ::);
        } else {
            asm volatile("cp.async.wait_group 0;\n" ::);
        }
        __syncthreads();

        const int s = kc & 1;
        const unsigned aHi = sptr(&As[s][0][0]);
        const unsigned aLo = sptr(&As[s][1][0]);
        const unsigned bHi = sptr(&Bs[s][0][0]);
        const unsigned bLo = sptr(&Bs[s][1][0]);

        unsigned ah[4][4], al[4][4], bh[2][4], bl[2][4];
#pragma unroll
        for (int mt = 0; mt < 4; mt++) {
            unsigned off = (unsigned)((wm + mt * 16) * AP * 2) + aoff;
            ldsm4(ah[mt], aHi + off);
            ldsm4(al[mt], aLo + off);
        }
#pragma unroll
        for (int ng = 0; ng < 2; ng++) {
            unsigned off = boff + ng * 32;
            ldsm4t(bh[ng], bHi + off);
            ldsm4t(bl[ng], bLo + off);
        }
#pragma unroll
        for (int mt = 0; mt < 4; mt++)
#pragma unroll
            for (int nt = 0; nt < 4; nt++) {
                const int ng = nt >> 1, p = (nt & 1) * 2;
                mma_bf(acc[mt][nt], ah[mt], bh[ng][p], bh[ng][p + 1]);
                mma_bf(acc[mt][nt], ah[mt], bl[ng][p], bl[ng][p + 1]);
                mma_bf(acc[mt][nt], al[mt], bh[ng][p], bh[ng][p + 1]);
            }
        __syncthreads();
    }

    // ---------------- epilogue ----------------
#pragma unroll
    for (int mt = 0; mt < 4; mt++) {
        const int r0 = bm + wm + mt * 16 + (lane >> 2);
        if (MODE == 0) {
#pragma unroll
            for (int nt = 0; nt < 4; nt++) {
                const int col = bn + wn + nt * 8 + (lane & 3) * 2;
                float2 g2 = *(const float2*)&g_gate[col];
                float2 xv = *(const float2*)&x[(size_t)r0 * Dq + col];
                float ox = fmaf(acc[mt][nt][0] - xv.x, g2.x, xv.x);
                float oy = fmaf(acc[mt][nt][1] - xv.y, g2.y, xv.y);
                __nv_bfloat162 h, l;
                split2(ox, oy, h, l);
                *(__nv_bfloat162*)&g_xsh[(size_t)r0 * Dq + col] = h;
                *(__nv_bfloat162*)&g_xsl[(size_t)r0 * Dq + col] = l;
                float2 xw = *(const float2*)&x[(size_t)(r0 + 8) * Dq + col];
                ox = fmaf(acc[mt][nt][2] - xw.x, g2.x, xw.x);
                oy = fmaf(acc[mt][nt][3] - xw.y, g2.y, xw.y);
                split2(ox, oy, h, l);
                *(__nv_bfloat162*)&g_xsh[(size_t)(r0 + 8) * Dq + col] = h;
                *(__nv_bfloat162*)&g_xsl[(size_t)(r0 + 8) * Dq + col] = l;
            }
        } else if (MODE == 1) {
            const float mu0 = g_mu[r0], rs0 = g_rstd[r0];
            const float mu1 = g_mu[r0 + 8], rs1 = g_rstd[r0 + 8];
#pragma unroll
            for (int nt = 0; nt < 4; nt++) {
                const int col = wn + nt * 8 + (lane & 3) * 2;
                const int ch = col >> 1;
                const float cs0 = g_csum[col], cs1 = g_csum[col + 1];
                const float bs0 = g_bsum[col], bs1 = g_bsum[col + 1];
                const float ef = g_efvec[ch];
                {
                    float kk = rs0 * (acc[mt][nt][0] - mu0 * cs0) + bs0;
                    float vv = rs0 * (acc[mt][nt][1] - mu0 * cs1) + bs1;
                    float sig = 1.f / (1.f + expf(-kk));
                    g_wkv[(size_t)r0 * DS + ch] = expf(-ef * sig) * vv;
                }
                {
                    float kk = rs1 * (acc[mt][nt][2] - mu1 * cs0) + bs0;
                    float vv = rs1 * (acc[mt][nt][3] - mu1 * cs1) + bs1;
                    float sig = 1.f / (1.f + expf(-kk));
                    g_wkv[(size_t)(r0 + 8) * DS + ch] = expf(-ef * sig) * vv;
                }
            }
        } else {
#pragma unroll
            for (int nt = 0; nt < 4; nt++) {
                const int col = bn + wn + nt * 8 + (lane & 3) * 2;
                float2 o0 = {acc[mt][nt][0], acc[mt][nt][1]};
                float2 o1 = {acc[mt][nt][2], acc[mt][nt][3]};
                *(float2*)&out[(size_t)r0 * Dq + col] = o0;
                *(float2*)&out[(size_t)(r0 + 8) * Dq + col] = o1;
            }
        }
    }
}

// ---------------------------------------------------------------------------
// LN stats: one warp per row, reconstruct hi+lo
// ---------------------------------------------------------------------------
__global__ void stats_kernel() {
    int row = blockIdx.x * 8 + (threadIdx.x >> 5);
    int l = threadIdx.x & 31;
    const float4* ph = (const float4*)(g_xsh + (size_t)row * Dq);
    const float4* pl = (const float4*)(g_xsl + (size_t)row * Dq);
    float s = 0.f, s2 = 0.f;
#pragma unroll
    for (int i = 0; i < 4; i++) {
        float4 hv = ph[l + 32 * i];
        float4 lv = pl[l + 32 * i];
        const __nv_bfloat162* hp = (const __nv_bfloat162*)&hv;
        const __nv_bfloat162* lp = (const __nv_bfloat162*)&lv;
#pragma unroll
        for (int j = 0; j < 4; j++) {
            float2 h2 = __bfloat1622float2(hp[j]);
            float2 l2 = __bfloat1622float2(lp[j]);
            float v0 = h2.x + l2.x, v1 = h2.y + l2.y;
            s += v0 + v1;
            s2 += v0 * v0 + v1 * v1;
        }
    }
#pragma unroll
    for (int o = 16; o; o >>= 1) {
        s  += __shfl_xor_sync(0xffffffffu, s, o);
        s2 += __shfl_xor_sync(0xffffffffu, s2, o);
    }
    if (l == 0) {
        float mu  = s * (1.f / 1024.f);
        float var = s2 * (1.f / 1024.f) - mu * mu;
        g_mu[row]   = mu;
        g_rstd[row] = rsqrtf(var + 1e-5f);
    }
}

// ---------------------------------------------------------------------------
__global__ void scan_kernel() {
    int bc = blockIdx.x;
    int ch = threadIdx.x;
    float w = g_wvec[ch];
    size_t base = (size_t)bc * CHq * DS + ch;
    float h = 0.f;
    for (int i = 0; i < CHq; i++) {
        h = fmaf(h, w, g_wkv[base + (size_t)i * DS]);
        __nv_bfloat16 hh = __float2bfloat16(h);
        g_hsh[base + (size_t)i * DS] = hh;
        g_hsl[base + (size_t)i * DS] = __float2bfloat16(h - __bfloat162float(hh));
    }
}

// ---------------------------------------------------------------------------
__global__ void cstate_kernel() {
    int bc = blockIdx.x;
    int ch = threadIdx.x;
    const float* base = g_wkv + (size_t)bc * CHq * DS + ch;
    float s = 0.f;
    for (int d = 0; d < CHq; d++)
        s = fmaf(g_c1[d * DS + ch], base[(size_t)(CHq - 1 - d) * DS], s);
    g_cs[bc * DS + ch] = s;
}

__global__ void lstate_kernel(float* __restrict__ outls) {
    int b = blockIdx.x;
    int ch = threadIdx.x;
    float s = 0.f;
    for (int e = 0; e < Cq; e++)
        s = fmaf(g_c2[e * DS + ch], g_cs[((size_t)b * Cq + (Cq - 1 - e)) * DS + ch], s);
    outls[b * DS + ch] = s;
}

// ---------------------------------------------------------------------------
extern "C" void kernel_launch(void* const* d_in, const int* in_sizes, int n_in,
                              void* d_out, int out_size) {
    const float* x   = (const float*)d_in[0];
    const float* td  = (const float*)d_in[1];
    const float* tf  = (const float*)d_in[2];
    const float* Wk  = (const float*)d_in[3];
    const float* Wv  = (const float*)d_in[4];
    const float* Wo  = (const float*)d_in[5];
    const float* Wsh = (const float*)d_in[6];
    const float* sg  = (const float*)d_in[7];
    const float* lng = (const float*)d_in[8];
    const float* lnb = (const float*)d_in[9];
    float* out = (float*)d_out;

    prep_kernel<<<1, 128>>>(td, tf, Wk, Wv, lng, lnb, sg);
    coef_kernel<<<64, 128>>>(td);

    __nv_bfloat16 *xh, *xl, *wshh, *wshl, *woh, *wol;
    cudaGetSymbolAddress((void**)&xh,   g_xh);
    cudaGetSymbolAddress((void**)&xl,   g_xl);
    cudaGetSymbolAddress((void**)&wshh, g_wshh);
    cudaGetSymbolAddress((void**)&wshl, g_wshl);
    cudaGetSymbolAddress((void**)&woh,  g_woh);
    cudaGetSymbolAddress((void**)&wol,  g_wol);

    conv_split<<<(ROWS * Dq / 4) / 256, 256>>>(x, xh, xl);
    conv_split<<<(Dq * Dq / 4) / 256, 256>>>(Wsh, wshh, wshl);
    conv_split<<<(DS * Dq / 4) / 256, 256>>>(Wo, woh, wol);

    gemm_tc<0><<<dim3(Dq / 128, ROWS / 128), 256>>>(x, out);
    stats_kernel<<<ROWS / 8, 256>>>();
    gemm_tc<1><<<ROWS / 128, 256>>>(x, out);
    scan_kernel<<<Bq * Cq, DS>>>();
    gemm_tc<2><<<dim3(Dq / 128, ROWS / 128), 256>>>(x, out);
    cstate_kernel<<<Bq * Cq, DS>>>();
    if ((size_t)out_size >= OUT_ELEMS + (size_t)Bq * DS) {
        lstate_kernel<<<Bq, DS>>>(out + OUT_ELEMS);
    }
}

// round 5
// speedup vs baseline: 1.2724x; 1.0322x over previous
#include <cuda_runtime.h>
#include <cuda_bf16.h>
#include <math.h>

// Problem constants
#define Bq   4
#define Tq   8192
#define Dq   1024
#define DS   64
#define CHq  128
#define Cq   64
#define ROWS (Bq * Tq)
#define OUT_ELEMS ((size_t)ROWS * Dq)

// ---------------- scratch ----------------
__device__ __nv_bfloat16 g_xh[ROWS * Dq];    // x split hi
__device__ __nv_bfloat16 g_xl[ROWS * Dq];    // x split lo
__device__ __nv_bfloat16 g_xsh[ROWS * Dq];   // x_shift hi
__device__ __nv_bfloat16 g_xsl[ROWS * Dq];   // x_shift lo
__device__ __nv_bfloat16 g_wshh[Dq * Dq];    // Wshift hi
__device__ __nv_bfloat16 g_wshl[Dq * Dq];    // Wshift lo
__device__ __nv_bfloat16 g_woh[DS * Dq];     // Wo hi
__device__ __nv_bfloat16 g_wol[DS * Dq];     // Wo lo
__device__ __nv_bfloat16 g_W2h[Dq * 128];    // interleaved g*[Wk|Wv] hi
__device__ __nv_bfloat16 g_W2l[Dq * 128];    // interleaved g*[Wk|Wv] lo
__device__ __nv_bfloat16 g_hsh[ROWS * DS];   // hs hi
__device__ __nv_bfloat16 g_hsl[ROWS * DS];   // hs lo
__device__ float g_wkv[ROWS * DS];
__device__ float g_mu[ROWS];
__device__ float g_rstd[ROWS];
__device__ float g_csum[128];
__device__ float g_bsum[128];
__device__ float g_gate[Dq];
__device__ float g_wvec[DS];
__device__ float g_efvec[DS];
__device__ float g_c1[CHq * DS];
__device__ float g_c2[Cq * DS];
__device__ float g_cs[Bq * Cq * DS];

// ---------------------------------------------------------------------------
__device__ __forceinline__ void split2(float v0, float v1, __nv_bfloat162& h, __nv_bfloat162& l) {
    __nv_bfloat16 h0 = __float2bfloat16(v0);
    __nv_bfloat16 h1 = __float2bfloat16(v1);
    __nv_bfloat16 l0 = __float2bfloat16(v0 - __bfloat162float(h0));
    __nv_bfloat16 l1 = __float2bfloat16(v1 - __bfloat162float(h1));
    h = __halves2bfloat162(h0, h1);
    l = __halves2bfloat162(l0, l1);
}

// generic fp32 -> (hi, lo) bf16 split
__global__ void conv_split(const float* __restrict__ in, __nv_bfloat16* __restrict__ hi,
                           __nv_bfloat16* __restrict__ lo) {
    int i = blockIdx.x * blockDim.x + threadIdx.x;
    float4 v = ((const float4*)in)[i];
    __nv_bfloat162 h0, l0, h1, l1;
    split2(v.x, v.y, h0, l0);
    split2(v.z, v.w, h1, l1);
    ((__nv_bfloat162*)hi)[2 * i]     = h0;
    ((__nv_bfloat162*)hi)[2 * i + 1] = h1;
    ((__nv_bfloat162*)lo)[2 * i]     = l0;
    ((__nv_bfloat162*)lo)[2 * i + 1] = l1;
}

// ---------------------------------------------------------------------------
__global__ void prep_kernel(const float* __restrict__ td, const float* __restrict__ tf,
                            const float* __restrict__ Wk, const float* __restrict__ Wv,
                            const float* __restrict__ ln_g, const float* __restrict__ ln_b,
                            const float* __restrict__ sg) {
    int n = threadIdx.x;  // 128 threads
    if (n < DS) {
        g_wvec[n]  = expf(td[n]);
        g_efvec[n] = expf(tf[n]);
    }
    for (int i = n; i < Dq; i += 128)
        g_gate[i] = 1.f / (1.f + expf(-sg[i]));

    int j = n >> 1, isv = n & 1;
    float cs = 0.f, bs = 0.f;
    for (int k = 0; k < Dq; k++) {
        float wv = isv ? Wv[k * DS + j] : Wk[k * DS + j];
        float gk = ln_g[k];
        float w2 = gk * wv;
        __nv_bfloat16 h = __float2bfloat16(w2);
        g_W2h[k * 128 + n] = h;
        g_W2l[k * 128 + n] = __float2bfloat16(w2 - __bfloat162float(h));
        cs += w2;
        bs += ln_b[k] * wv;
    }
    g_csum[n] = cs;
    g_bsum[n] = bs;
}

// ---------------------------------------------------------------------------
__global__ void coef_kernel(const float* __restrict__ td) {
    int ch = blockIdx.x;
    int d  = threadIdx.x;
    __shared__ float p[CHq];
    float w = expf(td[ch]);
    p[d] = (d == 0) ? 1.f : 0.f;
    __syncthreads();
    for (int s = 1; s < CHq; s++) {
        float tmp = (d >= s) ? p[d - s] : 0.f;
        __syncthreads();
        if (d >= s) p[d] += w * tmp;
        __syncthreads();
    }
    g_c1[d * DS + ch] = p[d];

    float wc = expf(128.f * td[ch]);
    __syncthreads();
    if (d < Cq) p[d] = (d == 0) ? 1.f : 0.f;
    __syncthreads();
    for (int s = 1; s < Cq; s++) {
        float tmp = (d >= s && d < Cq) ? p[d - s] : 0.f;
        __syncthreads();
        if (d >= s && d < Cq) p[d] += wc * tmp;
        __syncthreads();
    }
    if (d < Cq) g_c2[d * DS + ch] = p[d];
}

// ---------------------------------------------------------------------------
// tensor-core machinery
// ---------------------------------------------------------------------------
__device__ __forceinline__ unsigned sptr(const void* p) {
    return (unsigned)__cvta_generic_to_shared(p);
}
__device__ __forceinline__ void ldsm4(unsigned* r, unsigned a) {
    asm volatile("ldmatrix.sync.aligned.m8n8.x4.shared.b16 {%0,%1,%2,%3},[%4];"
                 : "=r"(r[0]), "=r"(r[1]), "=r"(r[2]), "=r"(r[3]) : "r"(a));
}
__device__ __forceinline__ void ldsm4t(unsigned* r, unsigned a) {
    asm volatile("ldmatrix.sync.aligned.m8n8.x4.trans.shared.b16 {%0,%1,%2,%3},[%4];"
                 : "=r"(r[0]), "=r"(r[1]), "=r"(r[2]), "=r"(r[3]) : "r"(a));
}
__device__ __forceinline__ void mma_bf(float* c, const unsigned* a, unsigned b0, unsigned b1) {
    asm volatile("mma.sync.aligned.m16n8k16.row.col.f32.bf16.bf16.f32 "
                 "{%0,%1,%2,%3},{%4,%5,%6,%7},{%8,%9},{%0,%1,%2,%3};"
                 : "+f"(c[0]), "+f"(c[1]), "+f"(c[2]), "+f"(c[3])
                 : "r"(a[0]), "r"(a[1]), "r"(a[2]), "r"(a[3]), "r"(b0), "r"(b1));
}
__device__ __forceinline__ void cp16(unsigned s, const void* g) {
    asm volatile("cp.async.cg.shared.global [%0],[%1],16;\n" :: "r"(s), "l"(g));
}

#define AP 24    // A smem pitch (bf16)
#define BP 136   // B smem pitch (bf16)
#define ABYTES (128 * AP * 2)     // 6144
#define BBYTES (16 * BP * 2)      // 4352

// MODE 0: x_shift GEMM; MODE 1: kv GEMM; MODE 2: out GEMM
template <int MODE>
__global__ __launch_bounds__(256, 2)
void gemm_tc(const float* __restrict__ x, float* __restrict__ out) {
    __shared__ __nv_bfloat16 As[2][2][128 * AP];
    __shared__ __nv_bfloat16 Bs[2][2][16 * BP];

    const int t = threadIdx.x;
    const int lane = t & 31;
    const int wid = t >> 5;
    const int wm = (wid >> 2) * 64;
    const int wn = (wid & 3) * 32;
    const int bm = (MODE == 1 ? blockIdx.x : blockIdx.y) * 128;
    const int bn = (MODE == 1 ? 0 : blockIdx.x * 128);
    const int NCH = (MODE == 2 ? 4 : 64);

    // global pointers (pre-split bf16)
    const __nv_bfloat16 *Ah, *Al, *Bh, *Bl;
    size_t bpitch;
    {
        int r = bm + (t >> 1);
        if (MODE == 0) {
            int s = ((r >> 13) << 13) | (((r & (Tq - 1)) + Tq / 2) & (Tq - 1));
            Ah = g_xh + (size_t)s * Dq;
            Al = g_xl + (size_t)s * Dq;
        } else if (MODE == 1) {
            Ah = g_xsh + (size_t)r * Dq;
            Al = g_xsl + (size_t)r * Dq;
        } else {
            Ah = g_hsh + (size_t)r * DS;
            Al = g_hsl + (size_t)r * DS;
        }
        Ah += (t & 1) * 8;
        Al += (t & 1) * 8;
    }
    if (MODE == 0)      { Bh = g_wshh; Bl = g_wshl; bpitch = Dq;  }
    else if (MODE == 1) { Bh = g_W2h;  Bl = g_W2l;  bpitch = 128; }
    else                { Bh = g_woh;  Bl = g_wol;  bpitch = Dq;  }
    Bh += (size_t)(t >> 4) * bpitch + bn + (t & 15) * 8;
    Bl += (size_t)(t >> 4) * bpitch + bn + (t & 15) * 8;

    const unsigned aST = sptr(&As[0][0][0]) + (unsigned)(((t >> 1) * AP + (t & 1) * 8) * 2);
    const unsigned bST = sptr(&Bs[0][0][0]) + (unsigned)(((t >> 4) * BP + (t & 15) * 8) * 2);

    const unsigned aoff = (unsigned)(((lane & 15) * AP + ((lane >> 4) << 3)) * 2);
    const unsigned boff = (unsigned)(((lane & 15) * BP + wn + ((lane >> 4) << 3)) * 2);

    float acc[4][4][4];
#pragma unroll
    for (int i = 0; i < 4; i++)
#pragma unroll
        for (int j = 0; j < 4; j++)
#pragma unroll
            for (int e = 0; e < 4; e++) acc[i][j][e] = 0.f;

    auto LOAD = [&](int kc) {
        const int s = kc & 1;
        unsigned a0 = aST + (unsigned)(s * 2 * ABYTES);
        cp16(a0,          Ah + (size_t)kc * 16);
        cp16(a0 + ABYTES, Al + (size_t)kc * 16);
        unsigned b0 = bST + (unsigned)(s * 2 * BBYTES);
        cp16(b0,          Bh + (size_t)kc * 16 * bpitch);
        cp16(b0 + BBYTES, Bl + (size_t)kc * 16 * bpitch);
        asm volatile("cp.async.commit_group;\n" ::);
    };

    LOAD(0);
    for (int kc = 0; kc < NCH; kc++) {
        // Single barrier per chunk. The barrier proves all warps finished the
        // previous chunk's LDSM reads (their MMAs consumed the registers before
        // reaching the barrier), so LOAD(kc+1) may immediately overwrite the
        // stage read at iter kc-1.
        asm volatile("cp.async.wait_group 0;\n" ::);
        __syncthreads();
        if (kc + 1 < NCH) LOAD(kc + 1);   // overlaps with compute below

        const int s = kc & 1;
        const unsigned aHi = sptr(&As[s][0][0]);
        const unsigned aLo = sptr(&As[s][1][0]);
        const unsigned bHi = sptr(&Bs[s][0][0]);
        const unsigned bLo = sptr(&Bs[s][1][0]);

        unsigned ah[4][4], al[4][4], bh[2][4], bl[2][4];
#pragma unroll
        for (int mt = 0; mt < 4; mt++) {
            unsigned off = (unsigned)((wm + mt * 16) * AP * 2) + aoff;
            ldsm4(ah[mt], aHi + off);
            ldsm4(al[mt], aLo + off);
        }
#pragma unroll
        for (int ng = 0; ng < 2; ng++) {
            unsigned off = boff + ng * 32;
            ldsm4t(bh[ng], bHi + off);
            ldsm4t(bl[ng], bLo + off);
        }
#pragma unroll
        for (int mt = 0; mt < 4; mt++)
#pragma unroll
            for (int nt = 0; nt < 4; nt++) {
                const int ng = nt >> 1, p = (nt & 1) * 2;
                mma_bf(acc[mt][nt], ah[mt], bh[ng][p], bh[ng][p + 1]);
                mma_bf(acc[mt][nt], ah[mt], bl[ng][p], bl[ng][p + 1]);
                mma_bf(acc[mt][nt], al[mt], bh[ng][p], bh[ng][p + 1]);
            }
    }

    // ---------------- epilogue ----------------
#pragma unroll
    for (int mt = 0; mt < 4; mt++) {
        const int r0 = bm + wm + mt * 16 + (lane >> 2);
        if (MODE == 0) {
#pragma unroll
            for (int nt = 0; nt < 4; nt++) {
                const int col = bn + wn + nt * 8 + (lane & 3) * 2;
                float2 g2 = *(const float2*)&g_gate[col];
                float2 xv = *(const float2*)&x[(size_t)r0 * Dq + col];
                float ox = fmaf(acc[mt][nt][0] - xv.x, g2.x, xv.x);
                float oy = fmaf(acc[mt][nt][1] - xv.y, g2.y, xv.y);
                __nv_bfloat162 h, l;
                split2(ox, oy, h, l);
                *(__nv_bfloat162*)&g_xsh[(size_t)r0 * Dq + col] = h;
                *(__nv_bfloat162*)&g_xsl[(size_t)r0 * Dq + col] = l;
                float2 xw = *(const float2*)&x[(size_t)(r0 + 8) * Dq + col];
                ox = fmaf(acc[mt][nt][2] - xw.x, g2.x, xw.x);
                oy = fmaf(acc[mt][nt][3] - xw.y, g2.y, xw.y);
                split2(ox, oy, h, l);
                *(__nv_bfloat162*)&g_xsh[(size_t)(r0 + 8) * Dq + col] = h;
                *(__nv_bfloat162*)&g_xsl[(size_t)(r0 + 8) * Dq + col] = l;
            }
        } else if (MODE == 1) {
            const float mu0 = g_mu[r0], rs0 = g_rstd[r0];
            const float mu1 = g_mu[r0 + 8], rs1 = g_rstd[r0 + 8];
#pragma unroll
            for (int nt = 0; nt < 4; nt++) {
                const int col = wn + nt * 8 + (lane & 3) * 2;
                const int ch = col >> 1;
                const float cs0 = g_csum[col], cs1 = g_csum[col + 1];
                const float bs0 = g_bsum[col], bs1 = g_bsum[col + 1];
                const float ef = g_efvec[ch];
                {
                    float kk = rs0 * (acc[mt][nt][0] - mu0 * cs0) + bs0;
                    float vv = rs0 * (acc[mt][nt][1] - mu0 * cs1) + bs1;
                    float sig = 1.f / (1.f + expf(-kk));
                    g_wkv[(size_t)r0 * DS + ch] = expf(-ef * sig) * vv;
                }
                {
                    float kk = rs1 * (acc[mt][nt][2] - mu1 * cs0) + bs0;
                    float vv = rs1 * (acc[mt][nt][3] - mu1 * cs1) + bs1;
                    float sig = 1.f / (1.f + expf(-kk));
                    g_wkv[(size_t)(r0 + 8) * DS + ch] = expf(-ef * sig) * vv;
                }
            }
        } else {
#pragma unroll
            for (int nt = 0; nt < 4; nt++) {
                const int col = bn + wn + nt * 8 + (lane & 3) * 2;
                float2 o0 = {acc[mt][nt][0], acc[mt][nt][1]};
                float2 o1 = {acc[mt][nt][2], acc[mt][nt][3]};
                *(float2*)&out[(size_t)r0 * Dq + col] = o0;
                *(float2*)&out[(size_t)(r0 + 8) * Dq + col] = o1;
            }
        }
    }
}

// ---------------------------------------------------------------------------
// LN stats: one warp per row, reconstruct hi+lo
// ---------------------------------------------------------------------------
__global__ void stats_kernel() {
    int row = blockIdx.x * 8 + (threadIdx.x >> 5);
    int l = threadIdx.x & 31;
    const float4* ph = (const float4*)(g_xsh + (size_t)row * Dq);
    const float4* pl = (const float4*)(g_xsl + (size_t)row * Dq);
    float4 hv[4], lv[4];
#pragma unroll
    for (int i = 0; i < 4; i++) { hv[i] = ph[l + 32 * i]; lv[i] = pl[l + 32 * i]; }
    float s = 0.f, s2 = 0.f;
#pragma unroll
    for (int i = 0; i < 4; i++) {
        const __nv_bfloat162* hp = (const __nv_bfloat162*)&hv[i];
        const __nv_bfloat162* lp = (const __nv_bfloat162*)&lv[i];
#pragma unroll
        for (int j = 0; j < 4; j++) {
            float2 h2 = __bfloat1622float2(hp[j]);
            float2 l2 = __bfloat1622float2(lp[j]);
            float v0 = h2.x + l2.x, v1 = h2.y + l2.y;
            s += v0 + v1;
            s2 += v0 * v0 + v1 * v1;
        }
    }
#pragma unroll
    for (int o = 16; o; o >>= 1) {
        s  += __shfl_xor_sync(0xffffffffu, s, o);
        s2 += __shfl_xor_sync(0xffffffffu, s2, o);
    }
    if (l == 0) {
        float mu  = s * (1.f / 1024.f);
        float var = s2 * (1.f / 1024.f) - mu * mu;
        g_mu[row]   = mu;
        g_rstd[row] = rsqrtf(var + 1e-5f);
    }
}

// ---------------------------------------------------------------------------
__global__ void scan_kernel() {
    int bc = blockIdx.x;
    int ch = threadIdx.x;
    float w = g_wvec[ch];
    size_t base = (size_t)bc * CHq * DS + ch;
    float h = 0.f;
    for (int i = 0; i < CHq; i++) {
        h = fmaf(h, w, g_wkv[base + (size_t)i * DS]);
        __nv_bfloat16 hh = __float2bfloat16(h);
        g_hsh[base + (size_t)i * DS] = hh;
        g_hsl[base + (size_t)i * DS] = __float2bfloat16(h - __bfloat162float(hh));
    }
}

// ---------------------------------------------------------------------------
__global__ void cstate_kernel() {
    int bc = blockIdx.x;
    int ch = threadIdx.x;
    const float* base = g_wkv + (size_t)bc * CHq * DS + ch;
    float s = 0.f;
    for (int d = 0; d < CHq; d++)
        s = fmaf(g_c1[d * DS + ch], base[(size_t)(CHq - 1 - d) * DS], s);
    g_cs[bc * DS + ch] = s;
}

__global__ void lstate_kernel(float* __restrict__ outls) {
    int b = blockIdx.x;
    int ch = threadIdx.x;
    float s = 0.f;
    for (int e = 0; e < Cq; e++)
        s = fmaf(g_c2[e * DS + ch], g_cs[((size_t)b * Cq + (Cq - 1 - e)) * DS + ch], s);
    outls[b * DS + ch] = s;
}

// ---------------------------------------------------------------------------
extern "C" void kernel_launch(void* const* d_in, const int* in_sizes, int n_in,
                              void* d_out, int out_size) {
    const float* x   = (const float*)d_in[0];
    const float* td  = (const float*)d_in[1];
    const float* tf  = (const float*)d_in[2];
    const float* Wk  = (const float*)d_in[3];
    const float* Wv  = (const float*)d_in[4];
    const float* Wo  = (const float*)d_in[5];
    const float* Wsh = (const float*)d_in[6];
    const float* sg  = (const float*)d_in[7];
    const float* lng = (const float*)d_in[8];
    const float* lnb = (const float*)d_in[9];
    float* out = (float*)d_out;

    __nv_bfloat16 *xh, *xl, *wshh, *wshl, *woh, *wol;
    cudaGetSymbolAddress((void**)&xh,   g_xh);
    cudaGetSymbolAddress((void**)&xl,   g_xl);
    cudaGetSymbolAddress((void**)&wshh, g_wshh);
    cudaGetSymbolAddress((void**)&wshl, g_wshl);
    cudaGetSymbolAddress((void**)&woh,  g_woh);
    cudaGetSymbolAddress((void**)&wol,  g_wol);

    // launch order chosen so gemm_tc<0> is the 4th launch (ncu samples #4)
    conv_split<<<(ROWS * Dq / 4) / 256, 256>>>(x, xh, xl);          // 1
    conv_split<<<(Dq * Dq / 4) / 256, 256>>>(Wsh, wshh, wshl);      // 2
    prep_kernel<<<1, 128>>>(td, tf, Wk, Wv, lng, lnb, sg);          // 3
    gemm_tc<0><<<dim3(Dq / 128, ROWS / 128), 256>>>(x, out);        // 4 <- profiled
    coef_kernel<<<64, 128>>>(td);                                   // 5
    conv_split<<<(DS * Dq / 4) / 256, 256>>>(Wo, woh, wol);         // 6
    stats_kernel<<<ROWS / 8, 256>>>();                              // 7
    gemm_tc<1><<<ROWS / 128, 256>>>(x, out);                        // 8
    scan_kernel<<<Bq * Cq, DS>>>();                                 // 9
    gemm_tc<2><<<dim3(Dq / 128, ROWS / 128), 256>>>(x, out);        // 10
    cstate_kernel<<<Bq * Cq, DS>>>();                               // 11
    if ((size_t)out_size >= OUT_ELEMS + (size_t)Bq * DS) {
        lstate_kernel<<<Bq, DS>>>(out + OUT_ELEMS);                 // 12
    }
}